// round 14
// baseline (speedup 1.0000x reference)
#include <cuda_runtime.h>
#include <stdint.h>

#define NN    2048         // num_nodes
#define W     64           // words per bitmask row = NN/32
#define FDIM  8            // edge feature dim
#define RB    (NN / 4)     // row blocks in k_emit (4 rows each)
#define TAILB 128          // tail-fill blocks appended to k_emit's grid

__device__ uint32_t g_adj    [NN * W];   // zero at load; re-zeroed by k_attr
__device__ uint32_t g_comb   [NN * W];
__device__ int      g_rowcnt [NN];
__device__ int      g_wordoff[NN * W];   // global output pos of first bit in word

// ---------------------------------------------------------------------------
// init_attr: zero attr region [E_MAX, F] (streaming stores; gates only k_attr)
// ---------------------------------------------------------------------------
__global__ void k_init_attr(float* __restrict__ out, int emax)
{
    float* base = out + (int64_t)emax * 2;
    const int64_t n4 = ((int64_t)emax * FDIM) >> 2;
    const float4 zer = make_float4(0.f, 0.f, 0.f, 0.f);
    int64_t stride = (int64_t)gridDim.x * blockDim.x;
    for (int64_t i = (int64_t)blockIdx.x * blockDim.x + threadIdx.x;
         i < n4; i += stride)
        __stcs(((float4*)base) + i, zer);
}

// ---------------------------------------------------------------------------
// scatter: set adjacency bits
// ---------------------------------------------------------------------------
__global__ void k_scatter(const int* __restrict__ src,
                          const int* __restrict__ dst, int E)
{
    int e = blockIdx.x * blockDim.x + threadIdx.x;
    if (e >= E) return;
    int s = src[e], d = dst[e];
    atomicOr(&g_adj[s * W + (d >> 5)], 1u << (d & 31));
}

// ---------------------------------------------------------------------------
// expand: comb_row = A_row | ((OR over neighbors of A_nbr) & ~self)
// 512 blocks x 256 threads, 4 rows/block; neighbor compaction + MLP-8 ORs.
// ---------------------------------------------------------------------------
__global__ __launch_bounds__(256) void k_expand()
{
    __shared__ uint16_t nbr[4][NN];
    __shared__ int wtot[4][2];

    const int tid  = threadIdx.x;
    const int g    = tid >> 6;
    const int w    = tid & 63;
    const int r    = (blockIdx.x << 2) + g;
    const int lane = w & 31, hw = w >> 5;

    uint32_t a = g_adj[r * W + w];

    int pc = __popc(a);
    int x = pc;
    #pragma unroll
    for (int o = 1; o < 32; o <<= 1) {
        int v = __shfl_up_sync(0xffffffffu, x, o);
        if (lane >= o) x += v;
    }
    if (lane == 31) wtot[g][hw] = x;
    __syncthreads();
    int excl = x - pc + (hw ? wtot[g][0] : 0);
    int cnt  = wtot[g][0] + wtot[g][1];

    {
        int p = excl;
        uint32_t m = a;
        while (m) {
            int b = __ffs(m) - 1; m &= m - 1;
            nbr[g][p++] = (uint16_t)((w << 5) + b);
        }
    }
    __syncthreads();

    uint32_t acc = a;
    const uint16_t* nl = nbr[g];
    int j = 0;
    for (; j + 8 <= cnt; j += 8) {
        uint32_t v0 = g_adj[(int)nl[j+0] * W + w];
        uint32_t v1 = g_adj[(int)nl[j+1] * W + w];
        uint32_t v2 = g_adj[(int)nl[j+2] * W + w];
        uint32_t v3 = g_adj[(int)nl[j+3] * W + w];
        uint32_t v4 = g_adj[(int)nl[j+4] * W + w];
        uint32_t v5 = g_adj[(int)nl[j+5] * W + w];
        uint32_t v6 = g_adj[(int)nl[j+6] * W + w];
        uint32_t v7 = g_adj[(int)nl[j+7] * W + w];
        acc |= (v0 | v1) | (v2 | v3) | ((v4 | v5) | (v6 | v7));
    }
    for (; j < cnt; j++)
        acc |= g_adj[(int)nl[j] * W + w];

    uint32_t self = (w == (r >> 5)) ? (1u << (r & 31)) : 0u;
    uint32_t comb = a | (acc & ~self);
    g_comb[r * W + w] = comb;

    int t = __popc(comb);
    #pragma unroll
    for (int o = 16; o; o >>= 1) t += __shfl_down_sync(0xffffffffu, t, o);
    __syncthreads();
    if (lane == 0) wtot[g][hw] = t;
    __syncthreads();
    if (w == 0) g_rowcnt[r] = wtot[g][0] + wtot[g][1];
}

// ---------------------------------------------------------------------------
// emit: blocks [0,RB)        -> 4 rows each: one block-prefix over rcnt,
//                               per-row word-scan, write (row,col) + wordoff
//       blocks [RB,RB+TAILB) -> vectorized -1 fill of idx tail [count,emax)
// ---------------------------------------------------------------------------
__global__ __launch_bounds__(256) void k_emit(float* __restrict__ out, int emax)
{
    __shared__ int swsum[8];
    __shared__ int srow[4];
    __shared__ int sbase;
    __shared__ int etot[4][2];

    const int tid  = threadIdx.x;
    const int bid  = blockIdx.x;
    const int lane = tid & 31, wid = tid >> 5;

    float* rows = out;
    float* cols = out + emax;

    if (bid >= RB) {
        // ---- tail fill ------------------------------------------------------
        int partial = 0;
        #pragma unroll
        for (int i = tid; i < NN; i += 256)
            partial += g_rowcnt[i];
        #pragma unroll
        for (int o = 16; o; o >>= 1)
            partial += __shfl_down_sync(0xffffffffu, partial, o);
        if (lane == 0) swsum[wid] = partial;
        __syncthreads();
        if (tid == 0) {
            int s = 0;
            #pragma unroll
            for (int q = 0; q < 8; q++) s += swsum[q];
            sbase = s;
        }
        __syncthreads();
        int total = sbase;
        if (total > emax) total = emax;

        int tb = bid - RB;
        int a0 = (total + 3) & ~3;           // first 16B-aligned slot
        if (a0 > emax) a0 = emax;
        if (tb == 0 && tid < (a0 - total)) {
            rows[total + tid] = -1.f;
            cols[total + tid] = -1.f;
        }

        int n4    = (emax - a0) >> 2;
        int chunk = (n4 + TAILB - 1) / TAILB;
        int s4 = tb * chunk;
        int e4 = s4 + chunk; if (e4 > n4) e4 = n4;
        const float4 neg = make_float4(-1.f, -1.f, -1.f, -1.f);
        float4* r4 = (float4*)(rows + a0);
        float4* c4 = (float4*)(cols + a0);
        for (int i = s4 + tid; i < e4; i += 256) {
            r4[i] = neg;
            c4[i] = neg;
        }
        return;
    }

    // ---- row blocks: 4 rows each -------------------------------------------
    const int g  = tid >> 6;
    const int w  = tid & 63;
    const int r0 = bid << 2;
    const int r  = r0 + g;
    const int hw = w >> 5;

    uint32_t comb = g_comb[r * W + w];       // issue early

    // block prefix: sum rcnt[0..r0) with 256 coalesced-strided threads
    int partial = 0;
    for (int i = tid; i < r0; i += 256)
        partial += g_rowcnt[i];
    #pragma unroll
    for (int o = 16; o; o >>= 1)
        partial += __shfl_down_sync(0xffffffffu, partial, o);
    if (lane == 0) swsum[wid] = partial;
    if (tid < 4) srow[tid] = g_rowcnt[r0 + tid];
    __syncthreads();
    if (tid == 0) {
        int s = 0;
        #pragma unroll
        for (int q = 0; q < 8; q++) s += swsum[q];
        sbase = s;
    }
    __syncthreads();

    int row_base = sbase;
    #pragma unroll
    for (int q = 0; q < 4; q++) {
        if (q >= g) break;
        row_base += srow[q];
    }

    // per-row word-level exclusive scan (64 threads = warps 2g, 2g+1)
    int epc = __popc(comb);
    int ex = epc;
    #pragma unroll
    for (int o = 1; o < 32; o <<= 1) {
        int v = __shfl_up_sync(0xffffffffu, ex, o);
        if (lane >= o) ex += v;
    }
    if (lane == 31) etot[g][hw] = ex;
    __syncthreads();
    int wexcl = ex - epc + (hw ? etot[g][0] : 0);

    int p = row_base + wexcl;
    g_wordoff[r * W + w] = p;

    float fr = (float)r;
    uint32_t c = comb;
    while (c) {
        int b = __ffs(c) - 1; c &= c - 1;
        if (p >= emax) break;
        rows[p] = fr;
        cols[p] = (float)((w << 5) + b);
        p++;
    }
}

// ---------------------------------------------------------------------------
// attr: O(1) rank via g_wordoff, attr loads issued early; re-zeroes g_adj
// ---------------------------------------------------------------------------
__global__ __launch_bounds__(256) void k_attr(
    const int* __restrict__ src, const int* __restrict__ dst,
    const float* __restrict__ attr, float* __restrict__ out,
    int emax, int E)
{
    int e = blockIdx.x * blockDim.x + threadIdx.x;

    if (e * 4 < NN * W)
        ((uint4*)g_adj)[e] = make_uint4(0u, 0u, 0u, 0u);

    if (e >= E) return;
    int s = src[e], d = dst[e];

    const float4* ia = (const float4*)(attr + (int64_t)e * FDIM);
    float4 a0 = ia[0];
    float4 a1 = ia[1];

    int idx = s * W + (d >> 5);
    int wo  = g_wordoff[idx];
    uint32_t cm = g_comb[idx];

    int p = wo + __popc(cm & ((1u << (d & 31)) - 1u));
    if (p >= emax) return;

    float* oa = out + (int64_t)emax * 2 + (int64_t)p * FDIM;
    asm volatile("red.global.add.v4.f32 [%0], {%1,%2,%3,%4};"
                 :: "l"(oa), "f"(a0.x), "f"(a0.y), "f"(a0.z), "f"(a0.w)
                 : "memory");
    asm volatile("red.global.add.v4.f32 [%0], {%1,%2,%3,%4};"
                 :: "l"(oa + 4), "f"(a1.x), "f"(a1.y), "f"(a1.z), "f"(a1.w)
                 : "memory");
}

// ---------------------------------------------------------------------------
// Host-side resources (host objects only; created once at process start)
// ---------------------------------------------------------------------------
static cudaStream_t s_side;
static cudaEvent_t  ev_fork, ev_attr_init;
struct _ResInit {
    _ResInit() {
        cudaStreamCreateWithFlags(&s_side, cudaStreamNonBlocking);
        cudaEventCreateWithFlags(&ev_fork, cudaEventDisableTiming);
        cudaEventCreateWithFlags(&ev_attr_init, cudaEventDisableTiming);
    }
};
static _ResInit _res_init_once;

extern "C" void kernel_launch(void* const* d_in, const int* in_sizes, int n_in,
                              void* d_out, int out_size)
{
    const int*   ei   = (const int*)d_in[1];
    const float* attr = (const float*)d_in[2];
    const int E    = in_sizes[1] / 2;
    const int emax = out_size / (2 + FDIM);
    float* out = (float*)d_out;

    // side branch: attr-region zero fill (gates only k_attr)
    cudaEventRecord(ev_fork, 0);
    cudaStreamWaitEvent(s_side, ev_fork, 0);
    k_init_attr<<<1024, 256, 0, s_side>>>(out, emax);
    cudaEventRecord(ev_attr_init, s_side);

    // main: scatter -> expand -> emit(+tail fill) -> attr (after attr init)
    k_scatter<<<(E + 255) / 256, 256>>>(ei, ei + E, E);
    k_expand <<<NN / 4, 256>>>();
    k_emit   <<<RB + TAILB, 256>>>(out, emax);
    cudaStreamWaitEvent(0, ev_attr_init, 0);
    k_attr   <<<(E + 255) / 256, 256>>>(ei, ei + E, attr, out, emax, E);
}

// round 16
// speedup vs baseline: 1.1632x; 1.1632x over previous
#include <cuda_runtime.h>
#include <stdint.h>

#define NN    2048         // num_nodes
#define W     64           // words per bitmask row = NN/32
#define FDIM  8            // edge feature dim
#define RB    (NN / 4)     // row blocks in k_emit (4 rows each)
#define TAILB 128          // tail-fill blocks appended to k_emit's grid

__device__ uint32_t g_adj    [NN * W];   // zero at load; re-zeroed by k_attr
__device__ uint32_t g_comb   [NN * W];
__device__ int      g_rowcnt [NN];
__device__ int      g_wordoff[NN * W];   // global output pos of first bit in word

// ---------------------------------------------------------------------------
// init_attr: zero attr region [E_MAX, F] (streaming stores; gates only k_attr)
// ---------------------------------------------------------------------------
__global__ void k_init_attr(float* __restrict__ out, int emax)
{
    float* base = out + (int64_t)emax * 2;
    const int64_t n4 = ((int64_t)emax * FDIM) >> 2;
    const float4 zer = make_float4(0.f, 0.f, 0.f, 0.f);
    int64_t stride = (int64_t)gridDim.x * blockDim.x;
    for (int64_t i = (int64_t)blockIdx.x * blockDim.x + threadIdx.x;
         i < n4; i += stride)
        __stcs(((float4*)base) + i, zer);
}

// ---------------------------------------------------------------------------
// scatter: set adjacency bits
// ---------------------------------------------------------------------------
__global__ void k_scatter(const int* __restrict__ src,
                          const int* __restrict__ dst, int E)
{
    int e = blockIdx.x * blockDim.x + threadIdx.x;
    if (e >= E) return;
    int s = src[e], d = dst[e];
    atomicOr(&g_adj[s * W + (d >> 5)], 1u << (d & 31));
}

// ---------------------------------------------------------------------------
// expand: comb_row = A_row | ((OR over neighbors of A_nbr) & ~self)
// 512 blocks x 256 threads, 4 rows/block; neighbor compaction + MLP-8 ORs.
// ---------------------------------------------------------------------------
__global__ __launch_bounds__(256) void k_expand()
{
    __shared__ uint16_t nbr[4][NN];
    __shared__ int wtot[4][2];

    const int tid  = threadIdx.x;
    const int g    = tid >> 6;
    const int w    = tid & 63;
    const int r    = (blockIdx.x << 2) + g;
    const int lane = w & 31, hw = w >> 5;

    uint32_t a = g_adj[r * W + w];

    int pc = __popc(a);
    int x = pc;
    #pragma unroll
    for (int o = 1; o < 32; o <<= 1) {
        int v = __shfl_up_sync(0xffffffffu, x, o);
        if (lane >= o) x += v;
    }
    if (lane == 31) wtot[g][hw] = x;
    __syncthreads();
    int excl = x - pc + (hw ? wtot[g][0] : 0);
    int cnt  = wtot[g][0] + wtot[g][1];

    {
        int p = excl;
        uint32_t m = a;
        while (m) {
            int b = __ffs(m) - 1; m &= m - 1;
            nbr[g][p++] = (uint16_t)((w << 5) + b);
        }
    }
    __syncthreads();

    uint32_t acc = a;
    const uint16_t* nl = nbr[g];
    int j = 0;
    for (; j + 8 <= cnt; j += 8) {
        uint32_t v0 = g_adj[(int)nl[j+0] * W + w];
        uint32_t v1 = g_adj[(int)nl[j+1] * W + w];
        uint32_t v2 = g_adj[(int)nl[j+2] * W + w];
        uint32_t v3 = g_adj[(int)nl[j+3] * W + w];
        uint32_t v4 = g_adj[(int)nl[j+4] * W + w];
        uint32_t v5 = g_adj[(int)nl[j+5] * W + w];
        uint32_t v6 = g_adj[(int)nl[j+6] * W + w];
        uint32_t v7 = g_adj[(int)nl[j+7] * W + w];
        acc |= (v0 | v1) | (v2 | v3) | ((v4 | v5) | (v6 | v7));
    }
    for (; j < cnt; j++)
        acc |= g_adj[(int)nl[j] * W + w];

    uint32_t self = (w == (r >> 5)) ? (1u << (r & 31)) : 0u;
    uint32_t comb = a | (acc & ~self);
    g_comb[r * W + w] = comb;

    int t = __popc(comb);
    #pragma unroll
    for (int o = 16; o; o >>= 1) t += __shfl_down_sync(0xffffffffu, t, o);
    __syncthreads();
    if (lane == 0) wtot[g][hw] = t;
    __syncthreads();
    if (w == 0) g_rowcnt[r] = wtot[g][0] + wtot[g][1];
}

// ---------------------------------------------------------------------------
// emit: row blocks stage col values in shared, then write rows/cols fully
// coalesced (streaming). Tail blocks fill idx tail [count,emax) with -1.
// ---------------------------------------------------------------------------
__global__ __launch_bounds__(256) void k_emit(float* __restrict__ out, int emax)
{
    __shared__ float sbuf[4 * NN];           // staged col values (32 KB)
    __shared__ int swsum[8];
    __shared__ int srow[4];
    __shared__ int sbase;
    __shared__ int etot[4][2];

    const int tid  = threadIdx.x;
    const int bid  = blockIdx.x;
    const int lane = tid & 31, wid = tid >> 5;

    float* rows = out;
    float* cols = out + emax;

    if (bid >= RB) {
        // ---- tail fill ------------------------------------------------------
        int partial = 0;
        #pragma unroll
        for (int i = tid; i < NN; i += 256)
            partial += g_rowcnt[i];
        #pragma unroll
        for (int o = 16; o; o >>= 1)
            partial += __shfl_down_sync(0xffffffffu, partial, o);
        if (lane == 0) swsum[wid] = partial;
        __syncthreads();
        if (tid == 0) {
            int s = 0;
            #pragma unroll
            for (int q = 0; q < 8; q++) s += swsum[q];
            sbase = s;
        }
        __syncthreads();
        int total = sbase;
        if (total > emax) total = emax;

        int tb = bid - RB;
        int a0 = (total + 3) & ~3;           // first 16B-aligned slot
        if (a0 > emax) a0 = emax;
        if (tb == 0 && tid < (a0 - total)) {
            rows[total + tid] = -1.f;
            cols[total + tid] = -1.f;
        }

        int n4    = (emax - a0) >> 2;
        int chunk = (n4 + TAILB - 1) / TAILB;
        int s4 = tb * chunk;
        int e4 = s4 + chunk; if (e4 > n4) e4 = n4;
        const float4 neg = make_float4(-1.f, -1.f, -1.f, -1.f);
        float4* r4 = (float4*)(rows + a0);
        float4* c4 = (float4*)(cols + a0);
        for (int i = s4 + tid; i < e4; i += 256) {
            __stcs(r4 + i, neg);
            __stcs(c4 + i, neg);
        }
        return;
    }

    // ---- row blocks: 4 rows each -------------------------------------------
    const int g  = tid >> 6;
    const int w  = tid & 63;
    const int r0 = bid << 2;
    const int r  = r0 + g;
    const int hw = w >> 5;

    uint32_t comb = g_comb[r * W + w];       // issue early

    // block prefix: sum rcnt[0..r0) with 256 coalesced-strided threads
    int partial = 0;
    for (int i = tid; i < r0; i += 256)
        partial += g_rowcnt[i];
    #pragma unroll
    for (int o = 16; o; o >>= 1)
        partial += __shfl_down_sync(0xffffffffu, partial, o);
    if (lane == 0) swsum[wid] = partial;
    if (tid < 4) srow[tid] = g_rowcnt[r0 + tid];
    __syncthreads();
    if (tid == 0) {
        int s = 0;
        #pragma unroll
        for (int q = 0; q < 8; q++) s += swsum[q];
        sbase = s;
    }
    __syncthreads();

    // block-local base of row g
    int lbase = 0;
    #pragma unroll
    for (int q = 0; q < 4; q++) {
        if (q >= g) break;
        lbase += srow[q];
    }

    // per-row word-level exclusive scan (64 threads = warps 2g, 2g+1)
    int epc = __popc(comb);
    int ex = epc;
    #pragma unroll
    for (int o = 1; o < 32; o <<= 1) {
        int v = __shfl_up_sync(0xffffffffu, ex, o);
        if (lane >= o) ex += v;
    }
    if (lane == 31) etot[g][hw] = ex;
    __syncthreads();
    int wexcl = ex - epc + (hw ? etot[g][0] : 0);

    g_wordoff[r * W + w] = sbase + lbase + wexcl;

    // stage col values into shared at block-local positions
    {
        int lp = lbase + wexcl;
        uint32_t c = comb;
        while (c) {
            int b = __ffs(c) - 1; c &= c - 1;
            sbuf[lp++] = (float)((w << 5) + b);
        }
    }
    __syncthreads();

    // coalesced copy-out with streaming stores
    int c1 = srow[0];
    int c2 = c1 + srow[1];
    int c3 = c2 + srow[2];
    int bsum = c3 + srow[3];
    int gb = sbase;
    float fr0 = (float)r0;
    for (int i = tid; i < bsum; i += 256) {
        int p = gb + i;
        if (p >= emax) break;
        float fr = fr0 + (float)((i >= c1) + (i >= c2) + (i >= c3));
        __stcs(rows + p, fr);
        __stcs(cols + p, sbuf[i]);
    }
}

// ---------------------------------------------------------------------------
// attr: O(1) rank via g_wordoff, attr loads issued early; re-zeroes g_adj
// ---------------------------------------------------------------------------
__global__ __launch_bounds__(256) void k_attr(
    const int* __restrict__ src, const int* __restrict__ dst,
    const float* __restrict__ attr, float* __restrict__ out,
    int emax, int E)
{
    int e = blockIdx.x * blockDim.x + threadIdx.x;

    if (e * 4 < NN * W)
        ((uint4*)g_adj)[e] = make_uint4(0u, 0u, 0u, 0u);

    if (e >= E) return;
    int s = src[e], d = dst[e];

    const float4* ia = (const float4*)(attr + (int64_t)e * FDIM);
    float4 a0 = ia[0];
    float4 a1 = ia[1];

    int idx = s * W + (d >> 5);
    int wo  = g_wordoff[idx];
    uint32_t cm = g_comb[idx];

    int p = wo + __popc(cm & ((1u << (d & 31)) - 1u));
    if (p >= emax) return;

    float* oa = out + (int64_t)emax * 2 + (int64_t)p * FDIM;
    asm volatile("red.global.add.v4.f32 [%0], {%1,%2,%3,%4};"
                 :: "l"(oa), "f"(a0.x), "f"(a0.y), "f"(a0.z), "f"(a0.w)
                 : "memory");
    asm volatile("red.global.add.v4.f32 [%0], {%1,%2,%3,%4};"
                 :: "l"(oa + 4), "f"(a1.x), "f"(a1.y), "f"(a1.z), "f"(a1.w)
                 : "memory");
}

// ---------------------------------------------------------------------------
// Host-side resources (host objects only; created once at process start)
// ---------------------------------------------------------------------------
static cudaStream_t s_side;
static cudaEvent_t  ev_fork, ev_attr_init;
struct _ResInit {
    _ResInit() {
        cudaStreamCreateWithFlags(&s_side, cudaStreamNonBlocking);
        cudaEventCreateWithFlags(&ev_fork, cudaEventDisableTiming);
        cudaEventCreateWithFlags(&ev_attr_init, cudaEventDisableTiming);
    }
};
static _ResInit _res_init_once;

extern "C" void kernel_launch(void* const* d_in, const int* in_sizes, int n_in,
                              void* d_out, int out_size)
{
    const int*   ei   = (const int*)d_in[1];
    const float* attr = (const float*)d_in[2];
    const int E    = in_sizes[1] / 2;
    const int emax = out_size / (2 + FDIM);
    float* out = (float*)d_out;

    // side branch: attr-region zero fill (gates only k_attr)
    cudaEventRecord(ev_fork, 0);
    cudaStreamWaitEvent(s_side, ev_fork, 0);
    k_init_attr<<<1024, 256, 0, s_side>>>(out, emax);
    cudaEventRecord(ev_attr_init, s_side);

    // main: scatter -> expand -> emit(+tail fill) -> attr (after attr init)
    k_scatter<<<(E + 255) / 256, 256>>>(ei, ei + E, E);
    k_expand <<<NN / 4, 256>>>();
    k_emit   <<<RB + TAILB, 256>>>(out, emax);
    cudaStreamWaitEvent(0, ev_attr_init, 0);
    k_attr   <<<(E + 255) / 256, 256>>>(ei, ei + E, attr, out, emax, E);
}